// round 4
// baseline (speedup 1.0000x reference)
#include <cuda_runtime.h>
#include <cuda_fp16.h>

// Problem constants
#define BB 256
#define DD 10
#define PP 1152
#define OO 16
#define DOX 160            // D*O
#define II 8
#define PCH 4              // p per CTA in k_uhat
#define NCH (PP / PCH)     // 288
#define BGRP 16            // b per CTA in k_uhat
#define BG 128             // b per group (L2-residency tile)
#define NBG (BG / BGRP)    // 8
#define NSL 8              // p slices per b in pass kernels
#define PSL (PP / NSL)     // 144

// Scratch
__device__ __half g_uhat_h[(size_t)BB * PP * DOX];   // 94.4 MB, [b][p][d*16+o]
__device__ float g_s1p[(size_t)BB * NCH * DOX];      // 47.2 MB (half hot at a time)
__device__ float g_spart[(size_t)BB * NSL * DOX];    // 1.3 MB
__device__ float g_va[(size_t)BB * DOX];             // v1

// ---------------------------------------------------------------------------
// Kernel 1: u_hat[b,p,do] = sum_i W[d,p,o,i] * x[b,p,i]  (fp16 store)
// + per-chunk fp32 s1 partials. Grid (NCH, NBG) x 160 thr; covers b0..b0+127.
// ---------------------------------------------------------------------------
__global__ void __launch_bounds__(DOX) k_uhat(const float* __restrict__ x,
                                              const float* __restrict__ W,
                                              int b0g) {
    const int c = blockIdx.x;
    const int t = threadIdx.x;
    const int d = t >> 4;
    const int o = t & 15;
    const int p0 = c * PCH;
    const int b0 = b0g + blockIdx.y * BGRP;

    float w[PCH][II];
#pragma unroll
    for (int ps = 0; ps < PCH; ps++) {
        const float4* wp = reinterpret_cast<const float4*>(
            W + (((size_t)d * PP + (size_t)(p0 + ps)) * OO + o) * II);
        float4 wa = wp[0], wb = wp[1];
        w[ps][0] = wa.x; w[ps][1] = wa.y; w[ps][2] = wa.z; w[ps][3] = wa.w;
        w[ps][4] = wb.x; w[ps][5] = wb.y; w[ps][6] = wb.z; w[ps][7] = wb.w;
    }

    __shared__ float xs[BGRP * PCH * II];   // 2 KB
    for (int idx = t; idx < BGRP * PCH * II; idx += DOX) {
        int bb = idx >> 5;                  // / (PCH*II = 32)
        int r = idx & 31;
        xs[idx] = x[((size_t)(b0 + bb) * PP + p0) * II + r];
    }
    __syncthreads();

#pragma unroll 2
    for (int bb = 0; bb < BGRP; bb++) {
        const float4* xb = reinterpret_cast<const float4*>(&xs[bb * PCH * II]);
        float acc = 0.f;
        __half* ud = g_uhat_h + ((size_t)(b0 + bb) * PP + p0) * DOX + t;
#pragma unroll
        for (int ps = 0; ps < PCH; ps++) {
            float4 xa = xb[ps * 2];
            float4 xc = xb[ps * 2 + 1];
            float u = w[ps][0] * xa.x + w[ps][1] * xa.y + w[ps][2] * xa.z + w[ps][3] * xa.w
                    + w[ps][4] * xc.x + w[ps][5] * xc.y + w[ps][6] * xc.z + w[ps][7] * xc.w;
            ud[(size_t)ps * DOX] = __float2half_rn(u);
            acc += u;
        }
        g_s1p[((size_t)(b0 + bb) * NCH + c) * DOX + t] = acc;
    }
}

// ---------------------------------------------------------------------------
__device__ __forceinline__ float squash_scale16(float s) {
    float sq = s * s;
    sq += __shfl_xor_sync(0xffffffffu, sq, 1);
    sq += __shfl_xor_sync(0xffffffffu, sq, 2);
    sq += __shfl_xor_sync(0xffffffffu, sq, 4);
    sq += __shfl_xor_sync(0xffffffffu, sq, 8);
    return sq / ((1.f + sq) * sqrtf(sq + 1e-7f));
}

// vred0: s1p -> v1 (g_va). Grid BG x 160; covers b0g..b0g+127.
__global__ void __launch_bounds__(DOX) k_vred0(int b0g) {
    const int b = b0g + blockIdx.x;
    const int t = threadIdx.x;
    float s = 0.f;
    const float* sp = g_s1p + (size_t)b * NCH * DOX + t;
#pragma unroll 4
    for (int c = 0; c < NCH; c++) s += sp[(size_t)c * DOX];
    s *= 0.1f;
    g_va[(size_t)b * DOX + t] = s * squash_scale16(s);
}

// vred2: spart -> squash -> out. Grid BB x 160 (all b, final).
__global__ void __launch_bounds__(DOX) k_vred2(float* __restrict__ out) {
    const int b = blockIdx.x;
    const int t = threadIdx.x;
    float s = 0.f;
    const float* sp = g_spart + (size_t)b * NSL * DOX + t;
#pragma unroll
    for (int c = 0; c < NSL; c++) s += sp[(size_t)c * DOX];
    out[(size_t)b * DOX + t] = s * squash_scale16(s);
}

// ---------------------------------------------------------------------------
// Pass kernel: s_partial[sl] = sum_{p in slice} softmax_d(u.v) * u
// which==0: v = v1.  which==1: v = v1 + squash(sum spart) in prologue.
// Lane layout: lane = ph*16 + d (d<10 valid). Grid (NSL, BG) x 256.
// ---------------------------------------------------------------------------
__device__ __forceinline__ float expp(float xv) {
    float r = fmaf(xv, 1.f / 24.f, 1.f / 6.f);
    r = fmaf(r, xv, 0.5f);
    r = fmaf(r, xv, 1.f);
    r = fmaf(r, xv, 1.f);
    return r;
}

__global__ void __launch_bounds__(256) k_pass(int which, int b0g) {
    const int sl = blockIdx.x;
    const int b = b0g + blockIdx.y;
    const int t = threadIdx.x;
    const int lane = t & 31;
    const int wid = t >> 5;              // 0..7
    const int ph = lane >> 4;            // p parity within warp
    const int d = lane & 15;
    const bool valid = d < DD;
    const int dd = valid ? d : 0;

    __shared__ float vsm[DOX];
    __shared__ float sred[8 * DOX];      // 5 KB

    if (t < DOX) {
        if (which == 0) {
            vsm[t] = g_va[(size_t)b * DOX + t];
        } else {
            float s = 0.f;
            const float* sp = g_spart + (size_t)b * NSL * DOX + t;
#pragma unroll
            for (int c = 0; c < NSL; c++) s += sp[(size_t)c * DOX];
            vsm[t] = g_va[(size_t)b * DOX + t] + s * squash_scale16(s);
        }
    }
    __syncthreads();

    // v row for this lane's d, as fp16 pairs (for HFMA2 dot)
    __half2 vh[8];
#pragma unroll
    for (int j = 0; j < 8; j++)
        vh[j] = __floats2half2_rn(vsm[dd * OO + 2 * j], vsm[dd * OO + 2 * j + 1]);

    float sa[OO];
#pragma unroll
    for (int o = 0; o < OO; o++) sa[o] = 0.f;

    const __half* ub = g_uhat_h + ((size_t)b * PP + (size_t)sl * PSL) * DOX;

#pragma unroll 3
    for (int it = 0; it < PSL / 16; it++) {
        const int p = it * 16 + wid * 2 + ph;
        const __half* up = ub + (size_t)p * DOX + dd * OO;

        __half2 u2[8];
        if (valid) {
            uint4 ra = *reinterpret_cast<const uint4*>(up);
            uint4 rb = *reinterpret_cast<const uint4*>(up + 8);
            u2[0] = *reinterpret_cast<const __half2*>(&ra.x);
            u2[1] = *reinterpret_cast<const __half2*>(&ra.y);
            u2[2] = *reinterpret_cast<const __half2*>(&ra.z);
            u2[3] = *reinterpret_cast<const __half2*>(&ra.w);
            u2[4] = *reinterpret_cast<const __half2*>(&rb.x);
            u2[5] = *reinterpret_cast<const __half2*>(&rb.y);
            u2[6] = *reinterpret_cast<const __half2*>(&rb.z);
            u2[7] = *reinterpret_cast<const __half2*>(&rb.w);
        } else {
#pragma unroll
            for (int j = 0; j < 8; j++) u2[j] = __half2half2(__float2half_rn(0.f));
        }

        // uv dot in fp16 (HFMA2 chain), tiny values -> negligible error
        __half2 hacc = __hmul2(u2[0], vh[0]);
#pragma unroll
        for (int j = 1; j < 8; j++) hacc = __hfma2(u2[j], vh[j], hacc);
        float2 hf = __half22float2(hacc);
        float uv = hf.x + hf.y;

        float e = valid ? expp(uv) : 0.f;
        float tot = e;
        tot += __shfl_xor_sync(0xffffffffu, tot, 1);
        tot += __shfl_xor_sync(0xffffffffu, tot, 2);
        tot += __shfl_xor_sync(0xffffffffu, tot, 4);
        tot += __shfl_xor_sync(0xffffffffu, tot, 8);
        float c = e * __fdividef(1.f, tot);

#pragma unroll
        for (int j = 0; j < 8; j++) {
            float2 f = __half22float2(u2[j]);
            sa[2 * j] = fmaf(c, f.x, sa[2 * j]);
            sa[2 * j + 1] = fmaf(c, f.y, sa[2 * j + 1]);
        }
    }

#pragma unroll
    for (int o = 0; o < OO; o++) sa[o] += __shfl_xor_sync(0xffffffffu, sa[o], 16);
    if (ph == 0 && valid) {
#pragma unroll
        for (int o = 0; o < OO; o++) sred[wid * DOX + d * OO + o] = sa[o];
    }
    __syncthreads();
    if (t < DOX) {
        float s = 0.f;
#pragma unroll
        for (int ww = 0; ww < 8; ww++) s += sred[ww * DOX + t];
        g_spart[((size_t)b * NSL + sl) * DOX + t] = s;
    }
}

// ---------------------------------------------------------------------------
extern "C" void kernel_launch(void* const* d_in, const int* in_sizes, int n_in,
                              void* d_out, int out_size) {
    const float* x = (const float*)d_in[0];   // [256, 1152, 8]
    const float* W = (const float*)d_in[1];   // [1, 10, 1152, 16, 8]
    float* out = (float*)d_out;               // [256, 10, 16]
    (void)in_sizes; (void)n_in; (void)out_size;

    for (int g = 0; g < BB / BG; g++) {
        const int b0g = g * BG;
        k_uhat<<<dim3(NCH, NBG), DOX>>>(x, W, b0g);
        k_vred0<<<BG, DOX>>>(b0g);
        k_pass<<<dim3(NSL, BG), 256>>>(0, b0g);   // pass A (v1)
        k_pass<<<dim3(NSL, BG), 256>>>(1, b0g);   // pass B (v1+v2)
    }
    k_vred2<<<BB, DOX>>>(out);
}

// round 5
// speedup vs baseline: 1.3571x; 1.3571x over previous
#include <cuda_runtime.h>
#include <cuda_fp16.h>

// Problem constants
#define BB 256
#define DD 10
#define PP 1152
#define OO 16
#define DOX 160            // D*O
#define II 8
#define PCH 8              // p per CTA in k_uhat
#define NCH (PP / PCH)     // 144
#define BGRP 32            // b per CTA in k_uhat
#define NBG (BB / BGRP)    // 8
#define NSL 8              // p slices per b in pass kernels
#define PSL (PP / NSL)     // 144

#define WN (DD * PP * OO * II)   // 1,474,560
#define XN (BB * PP * II)        // 2,359,296

// Scratch
__device__ __half g_uhat_h[(size_t)BB * PP * DOX];   // 94.4 MB, [b][p][d*16+o]
__device__ float g_s1p[(size_t)BB * NCH * DOX];      // 23.6 MB
__device__ float g_spart[(size_t)BB * NSL * DOX];    // 1.3 MB
__device__ float g_va[(size_t)BB * DOX];             // v1
__device__ __half g_Wh[(size_t)WN];                  // 2.95 MB
__device__ __half g_xh[(size_t)XN];                  // 4.7 MB
__device__ int g_cnt[BB];                            // zero-init, self-resetting

// ---------------------------------------------------------------------------
// Convert W and x to fp16 (vectorized float2 -> half2).
// ---------------------------------------------------------------------------
__global__ void __launch_bounds__(256) k_conv(const float* __restrict__ x,
                                              const float* __restrict__ W) {
    const int NW2 = WN / 2, NX2 = XN / 2;
    int i = blockIdx.x * blockDim.x + threadIdx.x;
    const int stride = gridDim.x * blockDim.x;
    for (; i < NW2 + NX2; i += stride) {
        if (i < NW2) {
            float2 f = reinterpret_cast<const float2*>(W)[i];
            reinterpret_cast<__half2*>(g_Wh)[i] = __floats2half2_rn(f.x, f.y);
        } else {
            float2 f = reinterpret_cast<const float2*>(x)[i - NW2];
            reinterpret_cast<__half2*>(g_xh)[i - NW2] = __floats2half2_rn(f.x, f.y);
        }
    }
}

// ---------------------------------------------------------------------------
// Kernel 1: u_hat[b,p,do] = sum_i W[d,p,o,i] * x[b,p,i]  (fp16 math + store)
// + per-chunk fp32 s1 partials. Grid (NCH, NBG) x 160 threads.
// ---------------------------------------------------------------------------
__global__ void __launch_bounds__(DOX, 8) k_uhat() {
    const int c = blockIdx.x;
    const int t = threadIdx.x;
    const int d = t >> 4;
    const int o = t & 15;
    const int p0 = c * PCH;
    const int b0 = blockIdx.y * BGRP;

    // W slice: 8 ps x 8 i halfs = one LDG.128 per ps
    __half2 w2[PCH][4];
#pragma unroll
    for (int ps = 0; ps < PCH; ps++) {
        uint4 r = *reinterpret_cast<const uint4*>(
            g_Wh + (((size_t)d * PP + (size_t)(p0 + ps)) * OO + o) * II);
        w2[ps][0] = *reinterpret_cast<__half2*>(&r.x);
        w2[ps][1] = *reinterpret_cast<__half2*>(&r.y);
        w2[ps][2] = *reinterpret_cast<__half2*>(&r.z);
        w2[ps][3] = *reinterpret_cast<__half2*>(&r.w);
    }

    __shared__ uint4 xs4[BGRP * PCH];   // 4 KB: [bb][ps] -> 8 halfs
    for (int idx = t; idx < BGRP * PCH; idx += DOX) {
        int bb = idx >> 3;
        int ps = idx & 7;
        xs4[idx] = *reinterpret_cast<const uint4*>(
            g_xh + ((size_t)(b0 + bb) * PP + (size_t)(p0 + ps)) * II);
    }
    __syncthreads();

    for (int bb = 0; bb < BGRP; bb++) {
        float acc = 0.f;
        __half* ud = g_uhat_h + ((size_t)(b0 + bb) * PP + p0) * DOX + t;
#pragma unroll
        for (int ps = 0; ps < PCH; ps++) {
            uint4 xr = xs4[bb * PCH + ps];
            __half2 a = __hmul2(w2[ps][0], *reinterpret_cast<__half2*>(&xr.x));
            a = __hfma2(w2[ps][1], *reinterpret_cast<__half2*>(&xr.y), a);
            a = __hfma2(w2[ps][2], *reinterpret_cast<__half2*>(&xr.z), a);
            a = __hfma2(w2[ps][3], *reinterpret_cast<__half2*>(&xr.w), a);
            float2 f = __half22float2(a);
            float u = f.x + f.y;
            ud[(size_t)ps * DOX] = __float2half_rn(u);
            acc += u;
        }
        g_s1p[((size_t)(b0 + bb) * NCH + c) * DOX + t] = acc;
    }
}

// ---------------------------------------------------------------------------
__device__ __forceinline__ float squash_scale16(float s) {
    float sq = s * s;
    sq += __shfl_xor_sync(0xffffffffu, sq, 1);
    sq += __shfl_xor_sync(0xffffffffu, sq, 2);
    sq += __shfl_xor_sync(0xffffffffu, sq, 4);
    sq += __shfl_xor_sync(0xffffffffu, sq, 8);
    return sq / ((1.f + sq) * sqrtf(sq + 1e-7f));
}

// vred0: s1p -> v1 (g_va). Grid BB x 160.
__global__ void __launch_bounds__(DOX) k_vred0() {
    const int b = blockIdx.x;
    const int t = threadIdx.x;
    float s = 0.f;
    const float* sp = g_s1p + (size_t)b * NCH * DOX + t;
#pragma unroll 4
    for (int c = 0; c < NCH; c++) s += sp[(size_t)c * DOX];
    s *= 0.1f;
    g_va[(size_t)b * DOX + t] = s * squash_scale16(s);
}

// ---------------------------------------------------------------------------
// Pass core: given v in vsm (smem), compute slice partial
// s = sum_{p in slice} softmax_d(u.v) * u  and write to g_spart[b][sl].
// ---------------------------------------------------------------------------
__device__ __forceinline__ float expp(float xv) {
    float r = fmaf(xv, 1.f / 24.f, 1.f / 6.f);
    r = fmaf(r, xv, 0.5f);
    r = fmaf(r, xv, 1.f);
    r = fmaf(r, xv, 1.f);
    return r;
}

__device__ __forceinline__ void pass_core(int b, int sl, const float* vsm,
                                          float* sred) {
    const int t = threadIdx.x;
    const int lane = t & 31;
    const int wid = t >> 5;
    const int ph = lane >> 4;
    const int d = lane & 15;
    const bool valid = d < DD;
    const int dd = valid ? d : 0;

    __half2 vh[8];
#pragma unroll
    for (int j = 0; j < 8; j++)
        vh[j] = __floats2half2_rn(vsm[dd * OO + 2 * j], vsm[dd * OO + 2 * j + 1]);

    float sa[OO];
#pragma unroll
    for (int o = 0; o < OO; o++) sa[o] = 0.f;

    const __half* ub = g_uhat_h + ((size_t)b * PP + (size_t)sl * PSL) * DOX;

#pragma unroll 3
    for (int it = 0; it < PSL / 16; it++) {
        const int p = it * 16 + wid * 2 + ph;
        const __half* up = ub + (size_t)p * DOX + dd * OO;

        __half2 u2[8];
        if (valid) {
            uint4 ra = *reinterpret_cast<const uint4*>(up);
            uint4 rb = *reinterpret_cast<const uint4*>(up + 8);
            u2[0] = *reinterpret_cast<const __half2*>(&ra.x);
            u2[1] = *reinterpret_cast<const __half2*>(&ra.y);
            u2[2] = *reinterpret_cast<const __half2*>(&ra.z);
            u2[3] = *reinterpret_cast<const __half2*>(&ra.w);
            u2[4] = *reinterpret_cast<const __half2*>(&rb.x);
            u2[5] = *reinterpret_cast<const __half2*>(&rb.y);
            u2[6] = *reinterpret_cast<const __half2*>(&rb.z);
            u2[7] = *reinterpret_cast<const __half2*>(&rb.w);
        } else {
#pragma unroll
            for (int j = 0; j < 8; j++) u2[j] = __half2half2(__float2half_rn(0.f));
        }

        // dot in two independent 4-deep HFMA2 chains
        __half2 h0 = __hmul2(u2[0], vh[0]);
        __half2 h1 = __hmul2(u2[1], vh[1]);
        h0 = __hfma2(u2[2], vh[2], h0);
        h1 = __hfma2(u2[3], vh[3], h1);
        h0 = __hfma2(u2[4], vh[4], h0);
        h1 = __hfma2(u2[5], vh[5], h1);
        h0 = __hfma2(u2[6], vh[6], h0);
        h1 = __hfma2(u2[7], vh[7], h1);
        float2 hf = __half22float2(__hadd2(h0, h1));
        float uv = hf.x + hf.y;

        float e = valid ? expp(uv) : 0.f;
        float tot = e;
        tot += __shfl_xor_sync(0xffffffffu, tot, 1);
        tot += __shfl_xor_sync(0xffffffffu, tot, 2);
        tot += __shfl_xor_sync(0xffffffffu, tot, 4);
        tot += __shfl_xor_sync(0xffffffffu, tot, 8);
        float c = e * __fdividef(1.f, tot);

#pragma unroll
        for (int j = 0; j < 8; j++) {
            float2 f = __half22float2(u2[j]);
            sa[2 * j] = fmaf(c, f.x, sa[2 * j]);
            sa[2 * j + 1] = fmaf(c, f.y, sa[2 * j + 1]);
        }
    }

#pragma unroll
    for (int o = 0; o < OO; o++) sa[o] += __shfl_xor_sync(0xffffffffu, sa[o], 16);
    if (ph == 0 && valid) {
#pragma unroll
        for (int o = 0; o < OO; o++) sred[wid * DOX + d * OO + o] = sa[o];
    }
    __syncthreads();
    if (t < DOX) {
        float s = 0.f;
#pragma unroll
        for (int ww = 0; ww < 8; ww++) s += sred[ww * DOX + t];
        g_spart[((size_t)b * NSL + sl) * DOX + t] = s;
    }
}

// Pass A: v = v1. Grid (NSL, BB) x 256.
__global__ void __launch_bounds__(256, 5) k_passA() {
    const int sl = blockIdx.x;
    const int b = blockIdx.y;
    const int t = threadIdx.x;
    __shared__ float vsm[DOX];
    __shared__ float sred[8 * DOX];
    if (t < DOX) vsm[t] = g_va[(size_t)b * DOX + t];
    __syncthreads();
    pass_core(b, sl, vsm, sred);
}

// Pass B: v = v1 + v2 (prologue-fused) and final squash -> out fused via
// deterministic last-CTA-per-b reduction (fixed summation order).
__global__ void __launch_bounds__(256, 5) k_passB(float* __restrict__ out) {
    const int sl = blockIdx.x;
    const int b = blockIdx.y;
    const int t = threadIdx.x;
    __shared__ float vsm[DOX];
    __shared__ float sred[8 * DOX];
    __shared__ int lastflag;

    if (t < DOX) {
        float s = 0.f;
        const float* sp = g_spart + (size_t)b * NSL * DOX + t;
#pragma unroll
        for (int c = 0; c < NSL; c++) s += sp[(size_t)c * DOX];
        vsm[t] = g_va[(size_t)b * DOX + t] + s * squash_scale16(s);
    }
    __syncthreads();
    pass_core(b, sl, vsm, sred);

    // epilogue: last CTA for this b performs the final reduce + squash
    __threadfence();
    if (t == 0) {
        int c = atomicAdd(&g_cnt[b], 1);
        lastflag = (c == NSL - 1);
        if (c == NSL - 1) g_cnt[b] = 0;   // reset for next graph replay
    }
    __syncthreads();
    if (lastflag) {
        __threadfence();
        if (t < DOX) {
            float s = 0.f;
            const float* sp = g_spart + (size_t)b * NSL * DOX + t;
#pragma unroll
            for (int c = 0; c < NSL; c++) s += sp[(size_t)c * DOX];
            out[(size_t)b * DOX + t] = s * squash_scale16(s);
        }
    }
}

// ---------------------------------------------------------------------------
extern "C" void kernel_launch(void* const* d_in, const int* in_sizes, int n_in,
                              void* d_out, int out_size) {
    const float* x = (const float*)d_in[0];   // [256, 1152, 8]
    const float* W = (const float*)d_in[1];   // [1, 10, 1152, 16, 8]
    float* out = (float*)d_out;               // [256, 10, 16]
    (void)in_sizes; (void)n_in; (void)out_size;

    k_conv<<<592, 256>>>(x, W);               // W,x -> fp16
    k_uhat<<<dim3(NCH, NBG), DOX>>>();        // u_hat + s1 partials
    k_vred0<<<BB, DOX>>>();                   // s1 -> v1
    k_passA<<<dim3(NSL, BB), 256>>>();        // pass A (v1)
    k_passB<<<dim3(NSL, BB), 256>>>(out);     // pass B + fused final squash
}

// round 6
// speedup vs baseline: 1.4804x; 1.0909x over previous
#include <cuda_runtime.h>
#include <cuda_fp16.h>

// Problem constants
#define BB 256
#define DD 10
#define PP 1152
#define OO 16
#define DOX 160            // D*O
#define II 8
#define PCH 8              // p per CTA in k_uhat
#define NCH (PP / PCH)     // 144
#define BGRP 32            // b per CTA in k_uhat
#define NBG (BB / BGRP)    // 8

// Scratch: u_hat fp16, [b][p][d*16+o]
__device__ __half g_uhat_h[(size_t)BB * PP * DOX];   // 94.4 MB

// ---------------------------------------------------------------------------
// Kernel 1: u_hat[b,p,do] = sum_i W[d,p,o,i] * x[b,p,i]; fp32 math, fp16 store.
// ps-outer / bb-inner: only 8 w-floats live -> low regs, high occupancy.
// Grid (NCH, NBG) x 160 threads.
// ---------------------------------------------------------------------------
__global__ void __launch_bounds__(DOX) k_uhat(const float* __restrict__ x,
                                              const float* __restrict__ W) {
    const int c = blockIdx.x;
    const int t = threadIdx.x;
    const int d = t >> 4;
    const int o = t & 15;
    const int p0 = c * PCH;
    const int b0 = blockIdx.y * BGRP;

    // x slice: [bb][ps][i] fp32, 8 KB; broadcast-read later (uniform per thread)
    __shared__ float xs[BGRP * PCH * II];
    for (int idx = t; idx < BGRP * PCH * II; idx += DOX) {
        int bb = idx >> 6;                  // / (PCH*II = 64)
        int r = idx & 63;
        xs[idx] = x[((size_t)(b0 + bb) * PP + p0) * II + r];
    }
    __syncthreads();

    __half* ucta = g_uhat_h + ((size_t)b0 * PP + p0) * DOX + t;

#pragma unroll
    for (int ps = 0; ps < PCH; ps++) {
        const float4* wp = reinterpret_cast<const float4*>(
            W + (((size_t)d * PP + (size_t)(p0 + ps)) * OO + o) * II);
        float4 wa = wp[0], wb = wp[1];
        __half* ud = ucta + (size_t)ps * DOX;
#pragma unroll 4
        for (int bb = 0; bb < BGRP; bb++) {
            const float4* xb = reinterpret_cast<const float4*>(&xs[bb * 64 + ps * 8]);
            float4 xa = xb[0], xc = xb[1];
            float u = wa.x * xa.x + wa.y * xa.y + wa.z * xa.z + wa.w * xa.w
                    + wb.x * xc.x + wb.y * xc.y + wb.z * xc.z + wb.w * xc.w;
            ud[(size_t)bb * PP * DOX] = __float2half_rn(u);
        }
    }
}

// ---------------------------------------------------------------------------
// Kernel 2: fully fused routing. One CTA per b (256 threads, 8 warps).
// sweep0: s1 = 0.1*sum_p u -> v1.  pass0: softmax(u.v1) -> v2, v=v1+v2.
// pass1: softmax(u.v) -> squash -> out.
// Lane layout: lane = ph*16 + d (valid d<10); warp handles 2 p per iter.
// ---------------------------------------------------------------------------
__device__ __forceinline__ float squash_scale16(float s) {
    float sq = s * s;
    sq += __shfl_xor_sync(0xffffffffu, sq, 1);
    sq += __shfl_xor_sync(0xffffffffu, sq, 2);
    sq += __shfl_xor_sync(0xffffffffu, sq, 4);
    sq += __shfl_xor_sync(0xffffffffu, sq, 8);
    return sq / ((1.f + sq) * sqrtf(sq + 1e-7f));
}

__device__ __forceinline__ float expp(float xv) {
    float r = fmaf(xv, 1.f / 24.f, 1.f / 6.f);
    r = fmaf(r, xv, 0.5f);
    r = fmaf(r, xv, 1.f);
    r = fmaf(r, xv, 1.f);
    return r;
}

__global__ void __launch_bounds__(256, 2) k_route(float* __restrict__ out) {
    const int b = blockIdx.x;
    const int t = threadIdx.x;
    const int lane = t & 31;
    const int wid = t >> 5;              // 0..7
    const int ph = lane >> 4;            // p parity within warp
    const int d = lane & 15;
    const bool valid = d < DD;
    const int dd = valid ? d : 0;

    __shared__ float vsm[DOX];           // current v
    __shared__ float v1sm[DOX];          // v1 kept for pass B prologue
    __shared__ float sred[8 * DOX];      // cross-warp partials (5 KB)

    const __half* ub = g_uhat_h + (size_t)b * PP * DOX;
    const __half* ulane = ub + (size_t)(wid * 2 + ph) * DOX + dd * OO;

    // ---- sweep 0: s1 = 0.1 * sum_p u ----
    {
        float sa[OO];
#pragma unroll
        for (int o = 0; o < OO; o++) sa[o] = 0.f;
#pragma unroll 4
        for (int it = 0; it < PP / 16; it++) {
            const __half* up = ulane + (size_t)it * 16 * DOX;
            if (valid) {
                uint4 ra = *reinterpret_cast<const uint4*>(up);
                uint4 rb = *reinterpret_cast<const uint4*>(up + 8);
                const unsigned rw[8] = {ra.x, ra.y, ra.z, ra.w, rb.x, rb.y, rb.z, rb.w};
#pragma unroll
                for (int j = 0; j < 8; j++) {
                    float2 f = __half22float2(*reinterpret_cast<const __half2*>(&rw[j]));
                    sa[2 * j] += f.x;
                    sa[2 * j + 1] += f.y;
                }
            }
        }
#pragma unroll
        for (int o = 0; o < OO; o++) sa[o] += __shfl_xor_sync(0xffffffffu, sa[o], 16);
        if (ph == 0 && valid) {
#pragma unroll
            for (int o = 0; o < OO; o++) sred[wid * DOX + d * OO + o] = sa[o];
        }
        __syncthreads();
        if (t < DOX) {
            float s = 0.f;
#pragma unroll
            for (int ww = 0; ww < 8; ww++) s += sred[ww * DOX + t];
            s *= 0.1f;
            float v = s * squash_scale16(s);
            v1sm[t] = v;
            vsm[t] = v;
        }
        __syncthreads();
    }

    // ---- routing passes ----
    for (int pass = 0; pass < 2; pass++) {
        __half2 vh[8];
#pragma unroll
        for (int j = 0; j < 8; j++)
            vh[j] = __floats2half2_rn(vsm[dd * OO + 2 * j], vsm[dd * OO + 2 * j + 1]);

        float sa[OO];
#pragma unroll
        for (int o = 0; o < OO; o++) sa[o] = 0.f;

#pragma unroll 4
        for (int it = 0; it < PP / 16; it++) {
            const __half* up = ulane + (size_t)it * 16 * DOX;
            __half2 u2[8];
            if (valid) {
                uint4 ra = *reinterpret_cast<const uint4*>(up);
                uint4 rb = *reinterpret_cast<const uint4*>(up + 8);
                u2[0] = *reinterpret_cast<const __half2*>(&ra.x);
                u2[1] = *reinterpret_cast<const __half2*>(&ra.y);
                u2[2] = *reinterpret_cast<const __half2*>(&ra.z);
                u2[3] = *reinterpret_cast<const __half2*>(&ra.w);
                u2[4] = *reinterpret_cast<const __half2*>(&rb.x);
                u2[5] = *reinterpret_cast<const __half2*>(&rb.y);
                u2[6] = *reinterpret_cast<const __half2*>(&rb.z);
                u2[7] = *reinterpret_cast<const __half2*>(&rb.w);
            } else {
#pragma unroll
                for (int j = 0; j < 8; j++) u2[j] = __half2half2(__float2half_rn(0.f));
            }

            // uv dot: two independent 4-deep HFMA2 chains
            __half2 h0 = __hmul2(u2[0], vh[0]);
            __half2 h1 = __hmul2(u2[1], vh[1]);
            h0 = __hfma2(u2[2], vh[2], h0);
            h1 = __hfma2(u2[3], vh[3], h1);
            h0 = __hfma2(u2[4], vh[4], h0);
            h1 = __hfma2(u2[5], vh[5], h1);
            h0 = __hfma2(u2[6], vh[6], h0);
            h1 = __hfma2(u2[7], vh[7], h1);
            float2 hf = __half22float2(__hadd2(h0, h1));
            float uv = hf.x + hf.y;

            float e = valid ? expp(uv) : 0.f;
            float tot = e;
            tot += __shfl_xor_sync(0xffffffffu, tot, 1);
            tot += __shfl_xor_sync(0xffffffffu, tot, 2);
            tot += __shfl_xor_sync(0xffffffffu, tot, 4);
            tot += __shfl_xor_sync(0xffffffffu, tot, 8);
            float cc = e * __fdividef(1.f, tot);

#pragma unroll
            for (int j = 0; j < 8; j++) {
                float2 f = __half22float2(u2[j]);
                sa[2 * j] = fmaf(cc, f.x, sa[2 * j]);
                sa[2 * j + 1] = fmaf(cc, f.y, sa[2 * j + 1]);
            }
        }

#pragma unroll
        for (int o = 0; o < OO; o++) sa[o] += __shfl_xor_sync(0xffffffffu, sa[o], 16);
        if (ph == 0 && valid) {
#pragma unroll
            for (int o = 0; o < OO; o++) sred[wid * DOX + d * OO + o] = sa[o];
        }
        __syncthreads();
        if (t < DOX) {
            float s = 0.f;
#pragma unroll
            for (int ww = 0; ww < 8; ww++) s += sred[ww * DOX + t];
            float v = s * squash_scale16(s);
            if (pass == 0) vsm[t] = v1sm[t] + v;          // v for pass B
            else           out[(size_t)b * DOX + t] = v;  // final output
        }
        __syncthreads();
    }
}

// ---------------------------------------------------------------------------
extern "C" void kernel_launch(void* const* d_in, const int* in_sizes, int n_in,
                              void* d_out, int out_size) {
    const float* x = (const float*)d_in[0];   // [256, 1152, 8]
    const float* W = (const float*)d_in[1];   // [1, 10, 1152, 16, 8]
    float* out = (float*)d_out;               // [256, 10, 16]
    (void)in_sizes; (void)n_in; (void)out_size;

    k_uhat<<<dim3(NCH, NBG), DOX>>>(x, W);
    k_route<<<BB, 256>>>(out);
}

// round 8
// speedup vs baseline: 1.7578x; 1.1874x over previous
#include <cuda_runtime.h>
#include <cuda_fp16.h>
#include <cstdint>

// Problem constants
#define BB 256
#define DD 10
#define PP 1152
#define OO 16
#define DOX 160            // D*O
#define II 8
#define PCH 8              // p per CTA in k_uhat
#define NCH (PP / PCH)     // 144
#define BGRP 32            // b per CTA in k_uhat
#define NBG (BB / BGRP)    // 8
#define HP (PP / 2)        // 576 p per half (cluster rank)
#define HCH (NCH / 2)      // 72 s1p chunks per half
#define NIT (HP / 16)      // 36 iterations per pass

// Scratch
__device__ __half g_uhat_h[(size_t)BB * PP * DOX];   // 94.4 MB, [b][p][d*16+o]
__device__ float g_s1p[(size_t)BB * NCH * DOX];      // 23.6 MB

// ---------------------------------------------------------------------------
// Kernel 1: u_hat = W.x (fp32 math, fp16 store) + per-chunk s1 partials.
// Grid (NCH, NBG) x 160 threads.
// ---------------------------------------------------------------------------
__global__ void __launch_bounds__(DOX) k_uhat(const float* __restrict__ x,
                                              const float* __restrict__ W) {
    const int c = blockIdx.x;
    const int t = threadIdx.x;
    const int d = t >> 4;
    const int o = t & 15;
    const int p0 = c * PCH;
    const int b0 = blockIdx.y * BGRP;

    float w[PCH][II];
#pragma unroll
    for (int ps = 0; ps < PCH; ps++) {
        const float4* wp = reinterpret_cast<const float4*>(
            W + (((size_t)d * PP + (size_t)(p0 + ps)) * OO + o) * II);
        float4 wa = wp[0], wb = wp[1];
        w[ps][0] = wa.x; w[ps][1] = wa.y; w[ps][2] = wa.z; w[ps][3] = wa.w;
        w[ps][4] = wb.x; w[ps][5] = wb.y; w[ps][6] = wb.z; w[ps][7] = wb.w;
    }

    __shared__ float xs[BGRP * PCH * II];   // 8 KB
    for (int idx = t; idx < BGRP * PCH * II; idx += DOX) {
        int bb = idx >> 6;
        int r = idx & 63;
        xs[idx] = x[((size_t)(b0 + bb) * PP + p0) * II + r];
    }
    __syncthreads();

    for (int bb = 0; bb < BGRP; bb++) {
        const float4* xb = reinterpret_cast<const float4*>(&xs[bb * 64]);
        float acc = 0.f;
        __half* ud = g_uhat_h + ((size_t)(b0 + bb) * PP + p0) * DOX + t;
#pragma unroll
        for (int ps = 0; ps < PCH; ps++) {
            float4 xa = xb[ps * 2];
            float4 xc = xb[ps * 2 + 1];
            float u = w[ps][0] * xa.x + w[ps][1] * xa.y + w[ps][2] * xa.z + w[ps][3] * xa.w
                    + w[ps][4] * xc.x + w[ps][5] * xc.y + w[ps][6] * xc.z + w[ps][7] * xc.w;
            ud[(size_t)ps * DOX] = __float2half_rn(u);
            acc += u;
        }
        g_s1p[((size_t)(b0 + bb) * NCH + c) * DOX + t] = acc;
    }
}

// ---------------------------------------------------------------------------
// Cluster helpers (PTX)
// ---------------------------------------------------------------------------
__device__ __forceinline__ unsigned smem_u32(const void* p) {
    unsigned a;
    asm("{ .reg .u64 tmp; cvta.to.shared.u64 tmp, %1; cvt.u32.u64 %0, tmp; }"
        : "=r"(a) : "l"(p));
    return a;
}
__device__ __forceinline__ float ld_peer_f32(unsigned local_addr, unsigned rank) {
    unsigned ra;
    asm("mapa.shared::cluster.u32 %0, %1, %2;" : "=r"(ra) : "r"(local_addr), "r"(rank));
    float v;
    asm volatile("ld.shared::cluster.f32 %0, [%1];" : "=f"(v) : "r"(ra));
    return v;
}
__device__ __forceinline__ void cluster_sync() {
    asm volatile("barrier.cluster.arrive.aligned;" ::: "memory");
    asm volatile("barrier.cluster.wait.aligned;" ::: "memory");
}

__device__ __forceinline__ float squash_scale16(float s) {
    float sq = s * s;
    sq += __shfl_xor_sync(0xffffffffu, sq, 1);
    sq += __shfl_xor_sync(0xffffffffu, sq, 2);
    sq += __shfl_xor_sync(0xffffffffu, sq, 4);
    sq += __shfl_xor_sync(0xffffffffu, sq, 8);
    return sq / ((1.f + sq) * sqrtf(sq + 1e-7f));
}

__device__ __forceinline__ float expp(float xv) {
    float r = fmaf(xv, 1.f / 24.f, 1.f / 6.f);
    r = fmaf(r, xv, 0.5f);
    r = fmaf(r, xv, 1.f);
    r = fmaf(r, xv, 1.f);
    return r;
}

// ---------------------------------------------------------------------------
// Kernel 2: fused routing, 2-CTA cluster per b (each CTA owns half of p).
// Grid 2*BB x 256 threads. Partial-s exchanged via DSMEM per stage.
// ---------------------------------------------------------------------------
__global__ void __launch_bounds__(256, 4) __cluster_dims__(2, 1, 1)
k_route(float* __restrict__ out) {
    const int b = blockIdx.x >> 1;
    const unsigned half = blockIdx.x & 1;
    const unsigned peer = half ^ 1u;
    const int t = threadIdx.x;
    const int lane = t & 31;
    const int wid = t >> 5;              // 0..7
    const int ph = lane >> 4;            // p parity within warp
    const int d = lane & 15;
    const bool valid = d < DD;
    const int dd = valid ? d : 0;

    __shared__ float vsm[DOX];
    __shared__ float v1sm[DOX];
    __shared__ float sred[8 * DOX];
    __shared__ float xbuf[3][DOX];       // one buffer per exchange

    // ---- stage 0: v1 from s1p (my half of chunks) ----
    {
        float s = 0.f;
        if (t < DOX) {
            const float* sp = g_s1p + ((size_t)b * NCH + half * HCH) * DOX + t;
#pragma unroll 4
            for (int c = 0; c < HCH; c++) s += sp[(size_t)c * DOX];
            xbuf[0][t] = s;
        }
        cluster_sync();
        if (t < DOX) {
            float tot = s + ld_peer_f32(smem_u32(&xbuf[0][t]), peer);
            tot *= 0.1f;
            float v = tot * squash_scale16(tot);
            v1sm[t] = v;
            vsm[t] = v;
        }
        __syncthreads();
    }

    const __half* ulane = g_uhat_h + ((size_t)b * PP + (size_t)half * HP
                                      + (size_t)(wid * 2 + ph)) * DOX + dd * OO;

    // ---- routing passes ----
    for (int pass = 0; pass < 2; pass++) {
        __half2 vh[8];
#pragma unroll
        for (int j = 0; j < 8; j++)
            vh[j] = __floats2half2_rn(vsm[dd * OO + 2 * j], vsm[dd * OO + 2 * j + 1]);

        float sa[OO];
#pragma unroll
        for (int o = 0; o < OO; o++) sa[o] = 0.f;

        // double-buffered prefetch; loads unconditional (invalid lanes read d=0
        // row — harmless broadcast; masked by e=0 below)
        const __half* up = ulane;
        uint4 ra = *reinterpret_cast<const uint4*>(up);
        uint4 rb = *reinterpret_cast<const uint4*>(up + 8);

#pragma unroll 1
        for (int it = 0; it < NIT; it++) {
            const __half* nup = up + (size_t)16 * DOX;
            uint4 na = ra, nb = rb;
            if (it + 1 < NIT) {
                na = *reinterpret_cast<const uint4*>(nup);
                nb = *reinterpret_cast<const uint4*>(nup + 8);
            }

            __half2 u2[8];
            u2[0] = *reinterpret_cast<const __half2*>(&ra.x);
            u2[1] = *reinterpret_cast<const __half2*>(&ra.y);
            u2[2] = *reinterpret_cast<const __half2*>(&ra.z);
            u2[3] = *reinterpret_cast<const __half2*>(&ra.w);
            u2[4] = *reinterpret_cast<const __half2*>(&rb.x);
            u2[5] = *reinterpret_cast<const __half2*>(&rb.y);
            u2[6] = *reinterpret_cast<const __half2*>(&rb.z);
            u2[7] = *reinterpret_cast<const __half2*>(&rb.w);

            __half2 h0 = __hmul2(u2[0], vh[0]);
            __half2 h1 = __hmul2(u2[1], vh[1]);
            h0 = __hfma2(u2[2], vh[2], h0);
            h1 = __hfma2(u2[3], vh[3], h1);
            h0 = __hfma2(u2[4], vh[4], h0);
            h1 = __hfma2(u2[5], vh[5], h1);
            h0 = __hfma2(u2[6], vh[6], h0);
            h1 = __hfma2(u2[7], vh[7], h1);
            float2 hf = __half22float2(__hadd2(h0, h1));
            float uv = hf.x + hf.y;

            float e = valid ? expp(uv) : 0.f;
            float tot = e;
            tot += __shfl_xor_sync(0xffffffffu, tot, 1);
            tot += __shfl_xor_sync(0xffffffffu, tot, 2);
            tot += __shfl_xor_sync(0xffffffffu, tot, 4);
            tot += __shfl_xor_sync(0xffffffffu, tot, 8);
            float cc = e * __fdividef(1.f, tot);

#pragma unroll
            for (int j = 0; j < 8; j++) {
                float2 f = __half22float2(u2[j]);
                sa[2 * j] = fmaf(cc, f.x, sa[2 * j]);
                sa[2 * j + 1] = fmaf(cc, f.y, sa[2 * j + 1]);
            }
            ra = na; rb = nb; up = nup;
        }

#pragma unroll
        for (int o = 0; o < OO; o++) sa[o] += __shfl_xor_sync(0xffffffffu, sa[o], 16);
        if (ph == 0 && valid) {
#pragma unroll
            for (int o = 0; o < OO; o++) sred[wid * DOX + d * OO + o] = sa[o];
        }
        __syncthreads();

        float s = 0.f;
        if (t < DOX) {
            for (int ww = 0; ww < 8; ww++) s += sred[ww * DOX + t];
            xbuf[pass + 1][t] = s;
        }
        cluster_sync();
        if (t < DOX) {
            float tot = s + ld_peer_f32(smem_u32(&xbuf[pass + 1][t]), peer);
            float v = tot * squash_scale16(tot);
            if (pass == 0) vsm[t] = v1sm[t] + v;
            else if (half == 0) out[(size_t)b * DOX + t] = v;
        }
        __syncthreads();
    }
    cluster_sync();   // keep smem alive until peer's last DSMEM read completes
}

// ---------------------------------------------------------------------------
extern "C" void kernel_launch(void* const* d_in, const int* in_sizes, int n_in,
                              void* d_out, int out_size) {
    const float* x = (const float*)d_in[0];   // [256, 1152, 8]
    const float* W = (const float*)d_in[1];   // [1, 10, 1152, 16, 8]
    float* out = (float*)d_out;               // [256, 10, 16]
    (void)in_sizes; (void)n_in; (void)out_size;

    k_uhat<<<dim3(NCH, NBG), DOX>>>(x, W);
    k_route<<<2 * BB, 256>>>(out);
}

// round 10
// speedup vs baseline: 1.8086x; 1.0289x over previous
#include <cuda_runtime.h>
#include <cuda_fp16.h>
#include <cstdint>

// Problem constants
#define BB 256
#define DD 10
#define PP 1152
#define OO 16
#define DOX 160            // D*O
#define II 8
#define PCH 8              // p per chunk in k_uhat
#define NCH (PP / PCH)     // 144
#define BGRP 64            // b per CTA in k_uhat
#define NBG (BB / BGRP)    // 4
#define HP (PP / 2)        // 576 p per cluster half
#define HCH (NCH / 2)      // 72 s1p chunks per half
#define NIT (HP / 8)       // 72 iterations per pass (1 p per warp-iter)

// Scratch (u_hat padded by one prefetch row-group)
__device__ __half g_uhat_h[(size_t)BB * PP * DOX + 16 * DOX];  // 94.4 MB
__device__ float g_s1p[(size_t)BB * NCH * DOX];                // 23.6 MB

// ---------------------------------------------------------------------------
// Kernel 1: u_hat = W.x (fp16 math + store) + per-chunk fp32 s1 partials.
// Grid (NCH, NBG) x 160 threads.
// ---------------------------------------------------------------------------
__global__ void __launch_bounds__(DOX) k_uhat(const float* __restrict__ x,
                                              const float* __restrict__ W) {
    const int c = blockIdx.x;
    const int t = threadIdx.x;
    const int d = t >> 4;
    const int o = t & 15;
    const int p0 = c * PCH;
    const int b0 = blockIdx.y * BGRP;

    // W slice -> fp16 pairs in regs (32 regs)
    __half2 w2[PCH][4];
#pragma unroll
    for (int ps = 0; ps < PCH; ps++) {
        const float4* wp = reinterpret_cast<const float4*>(
            W + (((size_t)d * PP + (size_t)(p0 + ps)) * OO + o) * II);
        float4 wa = wp[0], wb = wp[1];
        w2[ps][0] = __floats2half2_rn(wa.x, wa.y);
        w2[ps][1] = __floats2half2_rn(wa.z, wa.w);
        w2[ps][2] = __floats2half2_rn(wb.x, wb.y);
        w2[ps][3] = __floats2half2_rn(wb.z, wb.w);
    }

    // x slice -> fp16 in smem: [bb][ps] one uint4 (8 halfs), 8 KB
    __shared__ uint4 xs4[BGRP * PCH];
    for (int idx = t; idx < BGRP * PCH; idx += DOX) {
        int bb = idx >> 3;
        int ps = idx & 7;
        const float4* xp = reinterpret_cast<const float4*>(
            x + ((size_t)(b0 + bb) * PP + (size_t)(p0 + ps)) * II);
        float4 xa = xp[0], xb = xp[1];
        uint4 h;
        reinterpret_cast<__half2*>(&h)[0] = __floats2half2_rn(xa.x, xa.y);
        reinterpret_cast<__half2*>(&h)[1] = __floats2half2_rn(xa.z, xa.w);
        reinterpret_cast<__half2*>(&h)[2] = __floats2half2_rn(xb.x, xb.y);
        reinterpret_cast<__half2*>(&h)[3] = __floats2half2_rn(xb.z, xb.w);
        xs4[idx] = h;
    }
    __syncthreads();

    for (int bb = 0; bb < BGRP; bb++) {
        float acc = 0.f;
        __half* ud = g_uhat_h + ((size_t)(b0 + bb) * PP + p0) * DOX + t;
#pragma unroll
        for (int ps = 0; ps < PCH; ps++) {
            uint4 xr = xs4[bb * PCH + ps];
            __half2 a = __hmul2(w2[ps][0], *reinterpret_cast<__half2*>(&xr.x));
            a = __hfma2(w2[ps][1], *reinterpret_cast<__half2*>(&xr.y), a);
            a = __hfma2(w2[ps][2], *reinterpret_cast<__half2*>(&xr.z), a);
            a = __hfma2(w2[ps][3], *reinterpret_cast<__half2*>(&xr.w), a);
            __half u = __hadd(__low2half(a), __high2half(a));
            ud[(size_t)ps * DOX] = u;
            acc += __half2float(u);
        }
        g_s1p[((size_t)(b0 + bb) * NCH + c) * DOX + t] = acc;
    }
}

// ---------------------------------------------------------------------------
// Helpers
// ---------------------------------------------------------------------------
__device__ __forceinline__ unsigned smem_u32(const void* p) {
    unsigned a;
    asm("{ .reg .u64 tmp; cvta.to.shared.u64 tmp, %1; cvt.u32.u64 %0, tmp; }"
        : "=r"(a) : "l"(p));
    return a;
}
__device__ __forceinline__ float ld_peer_f32(unsigned local_addr, unsigned rank) {
    unsigned ra;
    asm("mapa.shared::cluster.u32 %0, %1, %2;" : "=r"(ra) : "r"(local_addr), "r"(rank));
    float v;
    asm volatile("ld.shared::cluster.f32 %0, [%1];" : "=f"(v) : "r"(ra));
    return v;
}
__device__ __forceinline__ void cluster_sync() {
    asm volatile("barrier.cluster.arrive.aligned;" ::: "memory");
    asm volatile("barrier.cluster.wait.aligned;" ::: "memory");
}
__device__ __forceinline__ void ffma2(unsigned long long& dst,
                                      unsigned long long a, unsigned long long b) {
    asm("fma.rn.f32x2 %0, %1, %2, %0;" : "+l"(dst) : "l"(a), "l"(b));
}
__device__ __forceinline__ unsigned long long pack2(float x, float y) {
    unsigned long long r;
    asm("mov.b64 %0, {%1, %2};" : "=l"(r) : "f"(x), "f"(y));
    return r;
}
__device__ __forceinline__ float2 unpack2(unsigned long long v) {
    float2 f;
    asm("mov.b64 {%0, %1}, %2;" : "=f"(f.x), "=f"(f.y) : "l"(v));
    return f;
}
__device__ __forceinline__ unsigned long long h2f2(unsigned h2bits) {
    float2 f = __half22float2(*reinterpret_cast<const __half2*>(&h2bits));
    return pack2(f.x, f.y);
}
__device__ __forceinline__ float squash_scale16(float s) {
    float sq = s * s;
    sq += __shfl_xor_sync(0xffffffffu, sq, 1);
    sq += __shfl_xor_sync(0xffffffffu, sq, 2);
    sq += __shfl_xor_sync(0xffffffffu, sq, 4);
    sq += __shfl_xor_sync(0xffffffffu, sq, 8);
    return sq / ((1.f + sq) * sqrtf(sq + 1e-7f));
}
__device__ __forceinline__ float expp(float xv) {
    float r = fmaf(xv, 1.f / 24.f, 1.f / 6.f);
    r = fmaf(r, xv, 0.5f);
    r = fmaf(r, xv, 1.f);
    r = fmaf(r, xv, 1.f);
    return r;
}

// ---------------------------------------------------------------------------
// Kernel 2: fused routing, 2-CTA cluster per b (each CTA owns half of p).
// Lane layout: lane = oh*16 + d (d<10 valid), lane owns 8 o's of one d-row.
// Warp processes ONE p per iteration; softmax total via 16-lane butterfly.
// Grid 2*BB x 256 threads.
// ---------------------------------------------------------------------------
__global__ void __launch_bounds__(256, 4) __cluster_dims__(2, 1, 1)
k_route(float* __restrict__ out) {
    const int b = blockIdx.x >> 1;
    const unsigned half = blockIdx.x & 1;
    const unsigned peer = half ^ 1u;
    const int t = threadIdx.x;
    const int lane = t & 31;
    const int wid = t >> 5;              // 0..7
    const int oh = lane >> 4;            // o-half (0: o 0-7, 1: o 8-15)
    const int d = lane & 15;
    const bool valid = d < DD;
    const int dd = valid ? d : 0;

    __shared__ float vsm[DOX];
    __shared__ float v1sm[DOX];
    __shared__ float sred[8 * DOX];
    __shared__ float xbuf[3][DOX];

    // ---- stage 0: v1 from s1p (my half of chunks) ----
    {
        float s = 0.f;
        if (t < DOX) {
            const float* sp = g_s1p + ((size_t)b * NCH + half * HCH) * DOX + t;
#pragma unroll 4
            for (int c = 0; c < HCH; c++) s += sp[(size_t)c * DOX];
            xbuf[0][t] = s;
        }
        cluster_sync();
        if (t < DOX) {
            float tot = s + ld_peer_f32(smem_u32(&xbuf[0][t]), peer);
            tot *= 0.1f;
            float v = tot * squash_scale16(tot);
            v1sm[t] = v;
            vsm[t] = v;
        }
        __syncthreads();
    }

    // lane's u_hat pointer: row p = wid + 8*it, element dd*16 + oh*8
    const __half* ulane = g_uhat_h + ((size_t)b * PP + (size_t)half * HP
                                      + (size_t)wid) * DOX + dd * OO + oh * 8;

    for (int pass = 0; pass < 2; pass++) {
        // v segment for this lane as packed f32x2
        unsigned long long v2[4];
        {
            const float4* vp = reinterpret_cast<const float4*>(&vsm[dd * OO + oh * 8]);
            float4 va = vp[0], vb = vp[1];
            v2[0] = pack2(va.x, va.y);
            v2[1] = pack2(va.z, va.w);
            v2[2] = pack2(vb.x, vb.y);
            v2[3] = pack2(vb.z, vb.w);
        }
        unsigned long long sa2[4] = {0ull, 0ull, 0ull, 0ull};

        const __half* up = ulane;
        uint4 cur = *reinterpret_cast<const uint4*>(up);

#pragma unroll 2
        for (int it = 0; it < NIT; it++) {
            up += 8 * DOX;                                   // next p row
            uint4 nxt = *reinterpret_cast<const uint4*>(up); // padded tail: safe

            unsigned long long u2[4];
            u2[0] = h2f2(cur.x);
            u2[1] = h2f2(cur.y);
            u2[2] = h2f2(cur.z);
            u2[3] = h2f2(cur.w);

            // partial dot over this lane's 8 o's (two independent chains)
            unsigned long long d0 = 0ull, d1 = 0ull;
            ffma2(d0, u2[0], v2[0]);
            ffma2(d1, u2[1], v2[1]);
            ffma2(d0, u2[2], v2[2]);
            ffma2(d1, u2[3], v2[3]);
            float2 f0 = unpack2(d0), f1 = unpack2(d1);
            float pd = (f0.x + f0.y) + (f1.x + f1.y);
            float uv = pd + __shfl_xor_sync(0xffffffffu, pd, 16);  // combine o-halves

            float e = valid ? expp(uv) : 0.f;
            // softmax denominator: sum of e over the 16-lane d-group
            float tot = e;
            tot += __shfl_xor_sync(0xffffffffu, tot, 1);
            tot += __shfl_xor_sync(0xffffffffu, tot, 2);
            tot += __shfl_xor_sync(0xffffffffu, tot, 4);
            tot += __shfl_xor_sync(0xffffffffu, tot, 8);
            float cc = __fdividef(e, tot);

            unsigned long long ccp = pack2(cc, cc);
            ffma2(sa2[0], ccp, u2[0]);
            ffma2(sa2[1], ccp, u2[1]);
            ffma2(sa2[2], ccp, u2[2]);
            ffma2(sa2[3], ccp, u2[3]);
            cur = nxt;
        }

        // write per-warp partials (each valid lane owns 8 distinct o's)
        if (valid) {
            float2 s0 = unpack2(sa2[0]), s1 = unpack2(sa2[1]);
            float2 s2 = unpack2(sa2[2]), s3 = unpack2(sa2[3]);
            float4* dst = reinterpret_cast<float4*>(&sred[wid * DOX + dd * OO + oh * 8]);
            dst[0] = make_float4(s0.x, s0.y, s1.x, s1.y);
            dst[1] = make_float4(s2.x, s2.y, s3.x, s3.y);
        }
        __syncthreads();

        float s = 0.f;
        if (t < DOX) {
#pragma unroll
            for (int ww = 0; ww < 8; ww++) s += sred[ww * DOX + t];
            xbuf[pass + 1][t] = s;
        }
        cluster_sync();
        if (t < DOX) {
            float tot = s + ld_peer_f32(smem_u32(&xbuf[pass + 1][t]), peer);
            float v = tot * squash_scale16(tot);
            if (pass == 0) vsm[t] = v1sm[t] + v;
            else if (half == 0) out[(size_t)b * DOX + t] = v;
        }
        __syncthreads();
    }
    cluster_sync();   // keep smem alive until peer's last DSMEM read completes
}

// ---------------------------------------------------------------------------
extern "C" void kernel_launch(void* const* d_in, const int* in_sizes, int n_in,
                              void* d_out, int out_size) {
    const float* x = (const float*)d_in[0];   // [256, 1152, 8]
    const float* W = (const float*)d_in[1];   // [1, 10, 1152, 16, 8]
    float* out = (float*)d_out;               // [256, 10, 16]
    (void)in_sizes; (void)n_in; (void)out_size;

    k_uhat<<<dim3(NCH, NBG), DOX>>>(x, W);
    k_route<<<2 * BB, 256>>>(out);
}

// round 11
// speedup vs baseline: 2.1774x; 1.2039x over previous
#include <cuda_runtime.h>
#include <cuda_fp16.h>
#include <cstdint>

// Problem constants
#define BB 256
#define DD 10
#define PP 1152
#define OO 16
#define DOX 160            // D*O
#define II 8
#define PCH 8              // p per chunk in k_uhat
#define NCH (PP / PCH)     // 144
#define BGRP 64            // b per CTA in k_uhat
#define NBG (BB / BGRP)    // 4
#define HP (PP / 2)        // 576 p per cluster half
#define HCH (NCH / 2)      // 72 s1p chunks per half
#define NIT (HP / 16)      // 36 warp-iterations per pass (2 p per iter)
#define NSEG 6             // fp16 accumulation segments per pass
#define SEGL (NIT / NSEG)  // 6 iterations per segment

// Scratch (u_hat padded by one prefetch row-group so tail prefetch is safe)
__device__ __half g_uhat_h[(size_t)BB * PP * DOX + 16 * DOX];  // 94.4 MB
__device__ float g_s1p[(size_t)BB * NCH * DOX];                // 23.6 MB

// ---------------------------------------------------------------------------
// Kernel 1: u_hat = W.x (fp16 math + store) + per-chunk fp32 s1 partials.
// Grid (NCH, NBG) x 160 threads.   (round-10 version, measured ~23 us)
// ---------------------------------------------------------------------------
__global__ void __launch_bounds__(DOX) k_uhat(const float* __restrict__ x,
                                              const float* __restrict__ W) {
    const int c = blockIdx.x;
    const int t = threadIdx.x;
    const int d = t >> 4;
    const int o = t & 15;
    const int p0 = c * PCH;
    const int b0 = blockIdx.y * BGRP;

    __half2 w2[PCH][4];
#pragma unroll
    for (int ps = 0; ps < PCH; ps++) {
        const float4* wp = reinterpret_cast<const float4*>(
            W + (((size_t)d * PP + (size_t)(p0 + ps)) * OO + o) * II);
        float4 wa = wp[0], wb = wp[1];
        w2[ps][0] = __floats2half2_rn(wa.x, wa.y);
        w2[ps][1] = __floats2half2_rn(wa.z, wa.w);
        w2[ps][2] = __floats2half2_rn(wb.x, wb.y);
        w2[ps][3] = __floats2half2_rn(wb.z, wb.w);
    }

    __shared__ uint4 xs4[BGRP * PCH];   // 8 KB
    for (int idx = t; idx < BGRP * PCH; idx += DOX) {
        int bb = idx >> 3;
        int ps = idx & 7;
        const float4* xp = reinterpret_cast<const float4*>(
            x + ((size_t)(b0 + bb) * PP + (size_t)(p0 + ps)) * II);
        float4 xa = xp[0], xb = xp[1];
        uint4 h;
        reinterpret_cast<__half2*>(&h)[0] = __floats2half2_rn(xa.x, xa.y);
        reinterpret_cast<__half2*>(&h)[1] = __floats2half2_rn(xa.z, xa.w);
        reinterpret_cast<__half2*>(&h)[2] = __floats2half2_rn(xb.x, xb.y);
        reinterpret_cast<__half2*>(&h)[3] = __floats2half2_rn(xb.z, xb.w);
        xs4[idx] = h;
    }
    __syncthreads();

    for (int bb = 0; bb < BGRP; bb++) {
        float acc = 0.f;
        __half* ud = g_uhat_h + ((size_t)(b0 + bb) * PP + p0) * DOX + t;
#pragma unroll
        for (int ps = 0; ps < PCH; ps++) {
            uint4 xr = xs4[bb * PCH + ps];
            __half2 a = __hmul2(w2[ps][0], *reinterpret_cast<__half2*>(&xr.x));
            a = __hfma2(w2[ps][1], *reinterpret_cast<__half2*>(&xr.y), a);
            a = __hfma2(w2[ps][2], *reinterpret_cast<__half2*>(&xr.z), a);
            a = __hfma2(w2[ps][3], *reinterpret_cast<__half2*>(&xr.w), a);
            __half u = __hadd(__low2half(a), __high2half(a));
            ud[(size_t)ps * DOX] = u;
            acc += __half2float(u);
        }
        g_s1p[((size_t)(b0 + bb) * NCH + c) * DOX + t] = acc;
    }
}

// ---------------------------------------------------------------------------
// Helpers
// ---------------------------------------------------------------------------
__device__ __forceinline__ unsigned smem_u32(const void* p) {
    unsigned a;
    asm("{ .reg .u64 tmp; cvta.to.shared.u64 tmp, %1; cvt.u32.u64 %0, tmp; }"
        : "=r"(a) : "l"(p));
    return a;
}
__device__ __forceinline__ float ld_peer_f32(unsigned local_addr, unsigned rank) {
    unsigned ra;
    asm("mapa.shared::cluster.u32 %0, %1, %2;" : "=r"(ra) : "r"(local_addr), "r"(rank));
    float v;
    asm volatile("ld.shared::cluster.f32 %0, [%1];" : "=f"(v) : "r"(ra));
    return v;
}
__device__ __forceinline__ void cluster_sync() {
    asm volatile("barrier.cluster.arrive.aligned;" ::: "memory");
    asm volatile("barrier.cluster.wait.aligned;" ::: "memory");
}
__device__ __forceinline__ float squash_scale16(float s) {
    float sq = s * s;
    sq += __shfl_xor_sync(0xffffffffu, sq, 1);
    sq += __shfl_xor_sync(0xffffffffu, sq, 2);
    sq += __shfl_xor_sync(0xffffffffu, sq, 4);
    sq += __shfl_xor_sync(0xffffffffu, sq, 8);
    return sq / ((1.f + sq) * sqrtf(sq + 1e-7f));
}
__device__ __forceinline__ float expp(float xv) {
    float r = fmaf(xv, 1.f / 24.f, 1.f / 6.f);
    r = fmaf(r, xv, 0.5f);
    r = fmaf(r, xv, 1.f);
    r = fmaf(r, xv, 1.f);
    return r;
}

// ---------------------------------------------------------------------------
// Kernel 2: fused routing, 2-CTA cluster per b (each CTA owns half of p).
// Round-8 layout: lane = ph*16 + d (d<10 valid); lane owns one full d-row
// (16 halfs) of one p; warp handles 2 p per iteration.
// NEW: fp16 segment accumulation (8 HFMA2/iter) flushed to fp32 every SEGL.
// Grid 2*BB x 256 threads.
// ---------------------------------------------------------------------------
__global__ void __launch_bounds__(256, 4) __cluster_dims__(2, 1, 1)
k_route(float* __restrict__ out) {
    const int b = blockIdx.x >> 1;
    const unsigned half = blockIdx.x & 1;
    const unsigned peer = half ^ 1u;
    const int t = threadIdx.x;
    const int lane = t & 31;
    const int wid = t >> 5;              // 0..7
    const int ph = lane >> 4;            // p parity within warp
    const int d = lane & 15;
    const bool valid = d < DD;
    const int dd = valid ? d : 0;

    __shared__ float vsm[DOX];
    __shared__ float v1sm[DOX];
    __shared__ float sred[8 * DOX];
    __shared__ float xbuf[3][DOX];

    // ---- stage 0: v1 from s1p (my half of chunks) ----
    {
        float s = 0.f;
        if (t < DOX) {
            const float* sp = g_s1p + ((size_t)b * NCH + half * HCH) * DOX + t;
#pragma unroll 4
            for (int c = 0; c < HCH; c++) s += sp[(size_t)c * DOX];
            xbuf[0][t] = s;
        }
        cluster_sync();
        if (t < DOX) {
            float tot = s + ld_peer_f32(smem_u32(&xbuf[0][t]), peer);
            tot *= 0.1f;
            float v = tot * squash_scale16(tot);
            v1sm[t] = v;
            vsm[t] = v;
        }
        __syncthreads();
    }

    const __half* ulane = g_uhat_h + ((size_t)b * PP + (size_t)half * HP
                                      + (size_t)(wid * 2 + ph)) * DOX + dd * OO;
    const __half2 hzero = __half2half2(__ushort_as_half((unsigned short)0));

    for (int pass = 0; pass < 2; pass++) {
        __half2 vh[8];
#pragma unroll
        for (int j = 0; j < 8; j++)
            vh[j] = __floats2half2_rn(vsm[dd * OO + 2 * j], vsm[dd * OO + 2 * j + 1]);

        float saf[OO];
#pragma unroll
        for (int o = 0; o < OO; o++) saf[o] = 0.f;

        const __half* up = ulane;
        uint4 ra = *reinterpret_cast<const uint4*>(up);
        uint4 rb = *reinterpret_cast<const uint4*>(up + 8);

        for (int seg = 0; seg < NSEG; seg++) {
            __half2 sa16[8];
#pragma unroll
            for (int j = 0; j < 8; j++) sa16[j] = hzero;

#pragma unroll
            for (int k = 0; k < SEGL; k++) {
                const __half* nup = up + (size_t)16 * DOX;
                // unconditional prefetch; buffer is padded past the end
                uint4 na = *reinterpret_cast<const uint4*>(nup);
                uint4 nb = *reinterpret_cast<const uint4*>(nup + 8);

                __half2 u2[8];
                u2[0] = *reinterpret_cast<const __half2*>(&ra.x);
                u2[1] = *reinterpret_cast<const __half2*>(&ra.y);
                u2[2] = *reinterpret_cast<const __half2*>(&ra.z);
                u2[3] = *reinterpret_cast<const __half2*>(&ra.w);
                u2[4] = *reinterpret_cast<const __half2*>(&rb.x);
                u2[5] = *reinterpret_cast<const __half2*>(&rb.y);
                u2[6] = *reinterpret_cast<const __half2*>(&rb.z);
                u2[7] = *reinterpret_cast<const __half2*>(&rb.w);

                // uv dot: two independent 4-deep HFMA2 chains
                __half2 h0 = __hmul2(u2[0], vh[0]);
                __half2 h1 = __hmul2(u2[1], vh[1]);
                h0 = __hfma2(u2[2], vh[2], h0);
                h1 = __hfma2(u2[3], vh[3], h1);
                h0 = __hfma2(u2[4], vh[4], h0);
                h1 = __hfma2(u2[5], vh[5], h1);
                h0 = __hfma2(u2[6], vh[6], h0);
                h1 = __hfma2(u2[7], vh[7], h1);
                float2 hf = __half22float2(__hadd2(h0, h1));
                float uv = hf.x + hf.y;

                float e = valid ? expp(uv) : 0.f;
                float tot = e;
                tot += __shfl_xor_sync(0xffffffffu, tot, 1);
                tot += __shfl_xor_sync(0xffffffffu, tot, 2);
                tot += __shfl_xor_sync(0xffffffffu, tot, 4);
                tot += __shfl_xor_sync(0xffffffffu, tot, 8);
                float cc = __fdividef(e, tot);

                // fp16 segment accumulation: 8 HFMA2
                __half2 cch = __half2half2(__float2half_rn(cc));
#pragma unroll
                for (int j = 0; j < 8; j++)
                    sa16[j] = __hfma2(cch, u2[j], sa16[j]);

                ra = na; rb = nb; up = nup;
            }

            // flush segment to fp32
#pragma unroll
            for (int j = 0; j < 8; j++) {
                float2 f = __half22float2(sa16[j]);
                saf[2 * j] += f.x;
                saf[2 * j + 1] += f.y;
            }
        }

#pragma unroll
        for (int o = 0; o < OO; o++) saf[o] += __shfl_xor_sync(0xffffffffu, saf[o], 16);
        if (ph == 0 && valid) {
#pragma unroll
            for (int o = 0; o < OO; o++) sred[wid * DOX + d * OO + o] = saf[o];
        }
        __syncthreads();

        float s = 0.f;
        if (t < DOX) {
#pragma unroll
            for (int ww = 0; ww < 8; ww++) s += sred[ww * DOX + t];
            xbuf[pass + 1][t] = s;
        }
        cluster_sync();
        if (t < DOX) {
            float tot = s + ld_peer_f32(smem_u32(&xbuf[pass + 1][t]), peer);
            float v = tot * squash_scale16(tot);
            if (pass == 0) vsm[t] = v1sm[t] + v;
            else if (half == 0) out[(size_t)b * DOX + t] = v;
        }
        __syncthreads();
    }
    cluster_sync();   // keep smem alive until peer's last DSMEM read completes
}

// ---------------------------------------------------------------------------
extern "C" void kernel_launch(void* const* d_in, const int* in_sizes, int n_in,
                              void* d_out, int out_size) {
    const float* x = (const float*)d_in[0];   // [256, 1152, 8]
    const float* W = (const float*)d_in[1];   // [1, 10, 1152, 16, 8]
    float* out = (float*)d_out;               // [256, 10, 16]
    (void)in_sizes; (void)n_in; (void)out_size;

    k_uhat<<<dim3(NCH, NBG), DOX>>>(x, W);
    k_route<<<2 * BB, 256>>>(out);
}